// round 1
// baseline (speedup 1.0000x reference)
#include <cuda_runtime.h>

#define BATCH 4
#define SEQ   2048
#define DMODEL 1024
#define NHEAD 16
#define DK    64
#define SCALE 0.125f
#define NEG_INF -1.0e9f

// ---------------- scratch (device globals; no allocation allowed) ----------------
__device__ float g_Q[(size_t)BATCH * NHEAD * SEQ * DK];   // 33.5 MB
__device__ float g_K[(size_t)BATCH * NHEAD * SEQ * DK];
__device__ float g_V[(size_t)BATCH * NHEAD * SEQ * DK];
__device__ float g_P[(size_t)BATCH * NHEAD * SEQ * SEQ];  // 1 GB probs
__device__ float g_C[(size_t)BATCH * SEQ * DMODEL];       // context [B,S,D]

// =====================================================================
// Projection: Y = X @ W^T, X [B*S, D], W [D, D] row-major (W[e,d]).
// Output written in [b, h, s, dk] layout for attention.
// grid (D/64, B*S/64), 256 threads.
// =====================================================================
__global__ __launch_bounds__(256) void proj_kernel(const float* __restrict__ X,
                                                   const float* __restrict__ W,
                                                   int which) {
    __shared__ float As[16][68];
    __shared__ float Bs[16][68];
    float* Out = (which == 0) ? g_Q : (which == 1) ? g_K : g_V;

    int tid = threadIdx.x;
    int tx = tid & 15, ty = tid >> 4;
    int m0 = blockIdx.y * 64;
    int n0 = blockIdx.x * 64;
    int lrow = tid >> 2;
    int lcol = (tid & 3) << 2;

    float acc[4][4];
#pragma unroll
    for (int i = 0; i < 4; i++)
#pragma unroll
        for (int j = 0; j < 4; j++) acc[i][j] = 0.f;

    const float* Arow = X + (size_t)(m0 + lrow) * DMODEL + lcol;
    const float* Brow = W + (size_t)(n0 + lrow) * DMODEL + lcol;

    for (int k0 = 0; k0 < DMODEL; k0 += 16) {
        float4 av = *(const float4*)(Arow + k0);
        float4 bv = *(const float4*)(Brow + k0);
        As[lcol + 0][lrow] = av.x; As[lcol + 1][lrow] = av.y;
        As[lcol + 2][lrow] = av.z; As[lcol + 3][lrow] = av.w;
        Bs[lcol + 0][lrow] = bv.x; Bs[lcol + 1][lrow] = bv.y;
        Bs[lcol + 2][lrow] = bv.z; Bs[lcol + 3][lrow] = bv.w;
        __syncthreads();
#pragma unroll
        for (int kk = 0; kk < 16; kk++) {
            float4 a = *(const float4*)&As[kk][ty << 2];
            float4 b = *(const float4*)&Bs[kk][tx << 2];
            float ar[4] = {a.x, a.y, a.z, a.w};
            float br[4] = {b.x, b.y, b.z, b.w};
#pragma unroll
            for (int i = 0; i < 4; i++)
#pragma unroll
                for (int j = 0; j < 4; j++) acc[i][j] += ar[i] * br[j];
        }
        __syncthreads();
    }

#pragma unroll
    for (int i = 0; i < 4; i++) {
        int m = m0 + (ty << 2) + i;
        int b = m >> 11;           // /SEQ
        int s = m & (SEQ - 1);
#pragma unroll
        for (int j = 0; j < 4; j++) {
            int e = n0 + (tx << 2) + j;
            int h = e >> 6;
            int dk = e & 63;
            Out[(((size_t)b * NHEAD + h) * SEQ + s) * DK + dk] = acc[i][j];
        }
    }
}

// =====================================================================
// Scores: S = scale * Q @ K^T, masked over key axis.
// grid (S/64, S/64, B*H), 256 threads. Kdim = 64.
// =====================================================================
__global__ __launch_bounds__(256) void scores_kernel(const int* __restrict__ mask) {
    __shared__ float As[16][68];
    __shared__ float Bs[16][68];

    int bh = blockIdx.z;
    int b = bh >> 4;
    const float* A = g_Q + (size_t)bh * SEQ * DK;
    const float* Bm = g_K + (size_t)bh * SEQ * DK;
    float* C = g_P + (size_t)bh * SEQ * SEQ;

    int tid = threadIdx.x;
    int tx = tid & 15, ty = tid >> 4;
    int m0 = blockIdx.y * 64;
    int n0 = blockIdx.x * 64;
    int lrow = tid >> 2;
    int lcol = (tid & 3) << 2;

    float acc[4][4];
#pragma unroll
    for (int i = 0; i < 4; i++)
#pragma unroll
        for (int j = 0; j < 4; j++) acc[i][j] = 0.f;

    const float* Arow = A + (size_t)(m0 + lrow) * DK + lcol;
    const float* Brow = Bm + (size_t)(n0 + lrow) * DK + lcol;

#pragma unroll
    for (int k0 = 0; k0 < DK; k0 += 16) {
        float4 av = *(const float4*)(Arow + k0);
        float4 bv = *(const float4*)(Brow + k0);
        As[lcol + 0][lrow] = av.x; As[lcol + 1][lrow] = av.y;
        As[lcol + 2][lrow] = av.z; As[lcol + 3][lrow] = av.w;
        Bs[lcol + 0][lrow] = bv.x; Bs[lcol + 1][lrow] = bv.y;
        Bs[lcol + 2][lrow] = bv.z; Bs[lcol + 3][lrow] = bv.w;
        __syncthreads();
#pragma unroll
        for (int kk = 0; kk < 16; kk++) {
            float4 a = *(const float4*)&As[kk][ty << 2];
            float4 b = *(const float4*)&Bs[kk][tx << 2];
            float ar[4] = {a.x, a.y, a.z, a.w};
            float br[4] = {b.x, b.y, b.z, b.w};
#pragma unroll
            for (int i = 0; i < 4; i++)
#pragma unroll
                for (int j = 0; j < 4; j++) acc[i][j] += ar[i] * br[j];
        }
        __syncthreads();
    }

    int mk[4];
#pragma unroll
    for (int j = 0; j < 4; j++) mk[j] = mask[b * SEQ + n0 + (tx << 2) + j];

#pragma unroll
    for (int i = 0; i < 4; i++) {
        int m = m0 + (ty << 2) + i;
#pragma unroll
        for (int j = 0; j < 4; j++) {
            int n = n0 + (tx << 2) + j;
            float v = acc[i][j] * SCALE;
            if (mk[j] == 0) v = NEG_INF;
            C[(size_t)m * SEQ + n] = v;
        }
    }
}

// =====================================================================
// Softmax in-place over g_P rows + head-mean written to out_mean.
// One block per (q, b); loops over all 16 heads so the mean
// accumulates in registers and is written exactly once.
// grid (SEQ, BATCH), 256 threads; 8 elements / thread / row.
// =====================================================================
__global__ __launch_bounds__(256) void softmax_mean_kernel(float* __restrict__ out_mean) {
    int q = blockIdx.x;
    int b = blockIdx.y;
    int tid = threadIdx.x;
    __shared__ float red[8];

    float meanacc[8];
#pragma unroll
    for (int i = 0; i < 8; i++) meanacc[i] = 0.f;

    for (int h = 0; h < NHEAD; h++) {
        float* row = g_P + (((size_t)(b * NHEAD + h)) * SEQ + q) * SEQ;
        float v[8];
        float mx = -3.4e38f;
#pragma unroll
        for (int i = 0; i < 8; i++) {
            v[i] = row[i * 256 + tid];
            mx = fmaxf(mx, v[i]);
        }
#pragma unroll
        for (int o = 16; o > 0; o >>= 1) mx = fmaxf(mx, __shfl_xor_sync(0xFFFFFFFFu, mx, o));
        if ((tid & 31) == 0) red[tid >> 5] = mx;
        __syncthreads();
        float m2 = red[0];
#pragma unroll
        for (int i = 1; i < 8; i++) m2 = fmaxf(m2, red[i]);
        __syncthreads();

        float sum = 0.f;
#pragma unroll
        for (int i = 0; i < 8; i++) {
            v[i] = __expf(v[i] - m2);
            sum += v[i];
        }
#pragma unroll
        for (int o = 16; o > 0; o >>= 1) sum += __shfl_xor_sync(0xFFFFFFFFu, sum, o);
        if ((tid & 31) == 0) red[tid >> 5] = sum;
        __syncthreads();
        float s2 = 0.f;
#pragma unroll
        for (int i = 0; i < 8; i++) s2 += red[i];
        __syncthreads();

        float inv = 1.0f / s2;
#pragma unroll
        for (int i = 0; i < 8; i++) {
            float p = v[i] * inv;
            row[i * 256 + tid] = p;
            meanacc[i] += p;
        }
    }

    float* om = out_mean + ((size_t)(b * SEQ + q)) * SEQ;
    const float invH = 1.0f / NHEAD;
#pragma unroll
    for (int i = 0; i < 8; i++) om[i * 256 + tid] = meanacc[i] * invH;
}

// =====================================================================
// Context: C = P @ V (NN gemm), per (b,h). M=S, N=64, K=S.
// Output to g_C in [B, S, D] layout (d = h*64 + n).
// grid (1, S/64, B*H), 256 threads.
// =====================================================================
__global__ __launch_bounds__(256) void ctx_kernel() {
    __shared__ float As[16][68];
    __shared__ float Bs[16][68];

    int bh = blockIdx.z;
    int b = bh >> 4;
    int h = bh & 15;
    const float* A = g_P + (size_t)bh * SEQ * SEQ;
    const float* Bmat = g_V + (size_t)bh * SEQ * DK;

    int tid = threadIdx.x;
    int tx = tid & 15, ty = tid >> 4;
    int m0 = blockIdx.y * 64;
    int lrow = tid >> 2;
    int lcol = (tid & 3) << 2;
    int brow = tid >> 4;          // 0..15 (k within tile)
    int bcol = (tid & 15) << 2;   // 0..60 (n)

    float acc[4][4];
#pragma unroll
    for (int i = 0; i < 4; i++)
#pragma unroll
        for (int j = 0; j < 4; j++) acc[i][j] = 0.f;

    const float* Arow = A + (size_t)(m0 + lrow) * SEQ + lcol;

    for (int k0 = 0; k0 < SEQ; k0 += 16) {
        float4 av = *(const float4*)(Arow + k0);
        As[lcol + 0][lrow] = av.x; As[lcol + 1][lrow] = av.y;
        As[lcol + 2][lrow] = av.z; As[lcol + 3][lrow] = av.w;
        float4 bv = *(const float4*)(Bmat + (size_t)(k0 + brow) * DK + bcol);
        *(float4*)&Bs[brow][bcol] = bv;
        __syncthreads();
#pragma unroll
        for (int kk = 0; kk < 16; kk++) {
            float4 a = *(const float4*)&As[kk][ty << 2];
            float4 bq = *(const float4*)&Bs[kk][tx << 2];
            float ar[4] = {a.x, a.y, a.z, a.w};
            float br[4] = {bq.x, bq.y, bq.z, bq.w};
#pragma unroll
            for (int i = 0; i < 4; i++)
#pragma unroll
                for (int j = 0; j < 4; j++) acc[i][j] += ar[i] * br[j];
        }
        __syncthreads();
    }

#pragma unroll
    for (int i = 0; i < 4; i++) {
        int m = m0 + (ty << 2) + i;
#pragma unroll
        for (int j = 0; j < 4; j++) {
            int n = (tx << 2) + j;
            g_C[((size_t)b * SEQ + m) * DMODEL + h * DK + n] = acc[i][j];
        }
    }
}

// =====================================================================
// Output projection: out = ctx @ W_o^T + b_o, written to d_out head.
// grid (D/64, B*S/64), 256 threads.
// =====================================================================
__global__ __launch_bounds__(256) void out_kernel(const float* __restrict__ Wo,
                                                  const float* __restrict__ bo,
                                                  float* __restrict__ out) {
    __shared__ float As[16][68];
    __shared__ float Bs[16][68];

    int tid = threadIdx.x;
    int tx = tid & 15, ty = tid >> 4;
    int m0 = blockIdx.y * 64;
    int n0 = blockIdx.x * 64;
    int lrow = tid >> 2;
    int lcol = (tid & 3) << 2;

    float acc[4][4];
#pragma unroll
    for (int i = 0; i < 4; i++)
#pragma unroll
        for (int j = 0; j < 4; j++) acc[i][j] = 0.f;

    const float* Arow = g_C + (size_t)(m0 + lrow) * DMODEL + lcol;
    const float* Brow = Wo + (size_t)(n0 + lrow) * DMODEL + lcol;

    for (int k0 = 0; k0 < DMODEL; k0 += 16) {
        float4 av = *(const float4*)(Arow + k0);
        float4 bv = *(const float4*)(Brow + k0);
        As[lcol + 0][lrow] = av.x; As[lcol + 1][lrow] = av.y;
        As[lcol + 2][lrow] = av.z; As[lcol + 3][lrow] = av.w;
        Bs[lcol + 0][lrow] = bv.x; Bs[lcol + 1][lrow] = bv.y;
        Bs[lcol + 2][lrow] = bv.z; Bs[lcol + 3][lrow] = bv.w;
        __syncthreads();
#pragma unroll
        for (int kk = 0; kk < 16; kk++) {
            float4 a = *(const float4*)&As[kk][ty << 2];
            float4 b = *(const float4*)&Bs[kk][tx << 2];
            float ar[4] = {a.x, a.y, a.z, a.w};
            float br[4] = {b.x, b.y, b.z, b.w};
#pragma unroll
            for (int i = 0; i < 4; i++)
#pragma unroll
                for (int j = 0; j < 4; j++) acc[i][j] += ar[i] * br[j];
        }
        __syncthreads();
    }

#pragma unroll
    for (int i = 0; i < 4; i++) {
        int m = m0 + (ty << 2) + i;
#pragma unroll
        for (int j = 0; j < 4; j++) {
            int e = n0 + (tx << 2) + j;
            out[(size_t)m * DMODEL + e] = acc[i][j] + bo[e];
        }
    }
}

// =====================================================================
extern "C" void kernel_launch(void* const* d_in, const int* in_sizes, int n_in,
                              void* d_out, int out_size) {
    const float* query = (const float*)d_in[0];
    const float* key   = (const float*)d_in[1];
    const float* value = (const float*)d_in[2];
    const int*   mask  = (const int*)d_in[3];
    const float* W_q   = (const float*)d_in[4];
    const float* W_k   = (const float*)d_in[5];
    const float* W_v   = (const float*)d_in[6];
    const float* W_o   = (const float*)d_in[7];
    const float* b_o   = (const float*)d_in[8];

    float* out_main = (float*)d_out;                                   // [B,S,D]
    float* out_mean = out_main + (size_t)BATCH * SEQ * DMODEL;          // [B,S,S]

    dim3 blk(256);
    dim3 gproj(DMODEL / 64, (BATCH * SEQ) / 64);

    proj_kernel<<<gproj, blk>>>(query, W_q, 0);
    proj_kernel<<<gproj, blk>>>(key,   W_k, 1);
    proj_kernel<<<gproj, blk>>>(value, W_v, 2);

    scores_kernel<<<dim3(SEQ / 64, SEQ / 64, BATCH * NHEAD), blk>>>(mask);

    softmax_mean_kernel<<<dim3(SEQ, BATCH), blk>>>(out_mean);

    ctx_kernel<<<dim3(1, SEQ / 64, BATCH * NHEAD), blk>>>();

    out_kernel<<<gproj, blk>>>(W_o, b_o, out_main);
}

// round 2
// speedup vs baseline: 1.2609x; 1.2609x over previous
#include <cuda_runtime.h>

#define BATCH 4
#define SEQ   2048
#define DMODEL 1024
#define NHEAD 16
#define DK    64
#define SCALE 0.125f
#define NEG_INF -1.0e9f

// ---------------- scratch (device globals; no allocation allowed) ----------------
__device__ float g_Q[(size_t)BATCH * NHEAD * SEQ * DK];
__device__ float g_K[(size_t)BATCH * NHEAD * SEQ * DK];
__device__ float g_V[(size_t)BATCH * NHEAD * SEQ * DK];
__device__ float g_P[(size_t)BATCH * NHEAD * SEQ * SEQ];  // 1 GB probs
__device__ float g_C[(size_t)BATCH * SEQ * DMODEL];       // context [B,S,D]

// =====================================================================
// 128x128x16 double-buffered SGEMM computing C = A @ B^T.
// A: [M,kdim] row-major, B: [N,kdim] row-major.
// 256 threads, 8x8 micro-tile per thread (4+4 split => conflict-free LDS.128).
// EPI 0: QKV projection (scatter to [b,h,s,dk]); EPI 1: scores (mask+scale
// into g_P per (b,h)=blockIdx.z); EPI 2: out-proj (+bias -> d_out).
// =====================================================================
template<int EPI>
__global__ __launch_bounds__(256, 2) void gemm128(
    const float* __restrict__ Ap, const float* __restrict__ Bp,
    const int* __restrict__ mask, const float* __restrict__ bias,
    float* __restrict__ Cp, int which)
{
    __shared__ __align__(16) float As[2][16][132];
    __shared__ __align__(16) float Bs[2][16][132];

    const int z = blockIdx.z;
    const float* A; const float* B; int lda, ldb, kdim;
    if constexpr (EPI == 0) { A = Ap; B = Bp; lda = DMODEL; ldb = DMODEL; kdim = DMODEL; }
    else if constexpr (EPI == 1) {
        A = g_Q + (size_t)z * SEQ * DK;
        B = g_K + (size_t)z * SEQ * DK;
        lda = DK; ldb = DK; kdim = DK;
    } else {
        A = g_C; B = Bp; lda = DMODEL; ldb = DMODEL; kdim = DMODEL;
    }

    const int tid = threadIdx.x;
    const int m0 = blockIdx.y * 128, n0 = blockIdx.x * 128;
    const int ldr = tid >> 1;            // 0..127
    const int ldc = (tid & 1) * 8;       // 0 or 8
    const int tx = tid & 15, ty = tid >> 4;

    const float* Aptr = A + (size_t)(m0 + ldr) * lda + ldc;
    const float* Bptr = B + (size_t)(n0 + ldr) * ldb + ldc;

    // preload tile 0
    {
        float4 a0 = *(const float4*)(Aptr);
        float4 a1 = *(const float4*)(Aptr + 4);
        float4 b0 = *(const float4*)(Bptr);
        float4 b1 = *(const float4*)(Bptr + 4);
        As[0][ldc+0][ldr]=a0.x; As[0][ldc+1][ldr]=a0.y; As[0][ldc+2][ldr]=a0.z; As[0][ldc+3][ldr]=a0.w;
        As[0][ldc+4][ldr]=a1.x; As[0][ldc+5][ldr]=a1.y; As[0][ldc+6][ldr]=a1.z; As[0][ldc+7][ldr]=a1.w;
        Bs[0][ldc+0][ldr]=b0.x; Bs[0][ldc+1][ldr]=b0.y; Bs[0][ldc+2][ldr]=b0.z; Bs[0][ldc+3][ldr]=b0.w;
        Bs[0][ldc+4][ldr]=b1.x; Bs[0][ldc+5][ldr]=b1.y; Bs[0][ldc+6][ldr]=b1.z; Bs[0][ldc+7][ldr]=b1.w;
    }
    __syncthreads();

    float acc[8][8];
#pragma unroll
    for (int i = 0; i < 8; i++)
#pragma unroll
        for (int j = 0; j < 8; j++) acc[i][j] = 0.f;

    const int ntiles = kdim >> 4;
    for (int t = 0; t < ntiles; t++) {
        const int cur = t & 1;
        float4 na0, na1, nb0, nb1;
        if (t + 1 < ntiles) {
            const float* ap = Aptr + (t + 1) * 16;
            na0 = *(const float4*)(ap);
            na1 = *(const float4*)(ap + 4);
            const float* bp = Bptr + (t + 1) * 16;
            nb0 = *(const float4*)(bp);
            nb1 = *(const float4*)(bp + 4);
        }
#pragma unroll
        for (int kk = 0; kk < 16; kk++) {
            float4 av0 = *(const float4*)&As[cur][kk][ty * 4];
            float4 av1 = *(const float4*)&As[cur][kk][64 + ty * 4];
            float4 bv0 = *(const float4*)&Bs[cur][kk][tx * 4];
            float4 bv1 = *(const float4*)&Bs[cur][kk][64 + tx * 4];
            float am[8] = {av0.x,av0.y,av0.z,av0.w, av1.x,av1.y,av1.z,av1.w};
            float bn[8] = {bv0.x,bv0.y,bv0.z,bv0.w, bv1.x,bv1.y,bv1.z,bv1.w};
#pragma unroll
            for (int i = 0; i < 8; i++)
#pragma unroll
                for (int j = 0; j < 8; j++) acc[i][j] += am[i] * bn[j];
        }
        if (t + 1 < ntiles) {
            const int nx = cur ^ 1;
            As[nx][ldc+0][ldr]=na0.x; As[nx][ldc+1][ldr]=na0.y; As[nx][ldc+2][ldr]=na0.z; As[nx][ldc+3][ldr]=na0.w;
            As[nx][ldc+4][ldr]=na1.x; As[nx][ldc+5][ldr]=na1.y; As[nx][ldc+6][ldr]=na1.z; As[nx][ldc+7][ldr]=na1.w;
            Bs[nx][ldc+0][ldr]=nb0.x; Bs[nx][ldc+1][ldr]=nb0.y; Bs[nx][ldc+2][ldr]=nb0.z; Bs[nx][ldc+3][ldr]=nb0.w;
            Bs[nx][ldc+4][ldr]=nb1.x; Bs[nx][ldc+5][ldr]=nb1.y; Bs[nx][ldc+6][ldr]=nb1.z; Bs[nx][ldc+7][ldr]=nb1.w;
        }
        __syncthreads();
    }

    if constexpr (EPI == 0) {
        float* Out = (which == 0) ? g_Q : (which == 1) ? g_K : g_V;
#pragma unroll
        for (int gi = 0; gi < 2; gi++)
#pragma unroll
            for (int i = 0; i < 4; i++) {
                int m = m0 + gi * 64 + ty * 4 + i;
                int b = m >> 11, s = m & (SEQ - 1);
#pragma unroll
                for (int gj = 0; gj < 2; gj++) {
                    int n = n0 + gj * 64 + tx * 4;
                    int h = n >> 6, dk = n & 63;
                    float4 v = make_float4(acc[gi*4+i][gj*4+0], acc[gi*4+i][gj*4+1],
                                           acc[gi*4+i][gj*4+2], acc[gi*4+i][gj*4+3]);
                    *(float4*)(Out + (((size_t)b * NHEAD + h) * SEQ + s) * DK + dk) = v;
                }
            }
    } else if constexpr (EPI == 1) {
        const int b = z >> 4;
        float* C = g_P + (size_t)z * SEQ * SEQ;
        int mk[2][4];
#pragma unroll
        for (int gj = 0; gj < 2; gj++)
#pragma unroll
            for (int j = 0; j < 4; j++)
                mk[gj][j] = mask[b * SEQ + n0 + gj * 64 + tx * 4 + j];
#pragma unroll
        for (int gi = 0; gi < 2; gi++)
#pragma unroll
            for (int i = 0; i < 4; i++) {
                int m = m0 + gi * 64 + ty * 4 + i;
#pragma unroll
                for (int gj = 0; gj < 2; gj++) {
                    int n = n0 + gj * 64 + tx * 4;
                    float4 v;
                    v.x = mk[gj][0] ? acc[gi*4+i][gj*4+0] * SCALE : NEG_INF;
                    v.y = mk[gj][1] ? acc[gi*4+i][gj*4+1] * SCALE : NEG_INF;
                    v.z = mk[gj][2] ? acc[gi*4+i][gj*4+2] * SCALE : NEG_INF;
                    v.w = mk[gj][3] ? acc[gi*4+i][gj*4+3] * SCALE : NEG_INF;
                    *(float4*)(C + (size_t)m * SEQ + n) = v;
                }
            }
    } else {
#pragma unroll
        for (int gi = 0; gi < 2; gi++)
#pragma unroll
            for (int i = 0; i < 4; i++) {
                int m = m0 + gi * 64 + ty * 4 + i;
#pragma unroll
                for (int gj = 0; gj < 2; gj++) {
                    int n = n0 + gj * 64 + tx * 4;
                    float4 bb = *(const float4*)(bias + n);
                    float4 v = make_float4(acc[gi*4+i][gj*4+0] + bb.x, acc[gi*4+i][gj*4+1] + bb.y,
                                           acc[gi*4+i][gj*4+2] + bb.z, acc[gi*4+i][gj*4+3] + bb.w);
                    *(float4*)(Cp + (size_t)m * DMODEL + n) = v;
                }
            }
    }
}

// =====================================================================
// Softmax in-place over g_P rows + head-mean written once (no atomics).
// grid (SEQ, BATCH), 256 threads.
// =====================================================================
__global__ __launch_bounds__(256) void softmax_mean_kernel(float* __restrict__ out_mean) {
    int q = blockIdx.x;
    int b = blockIdx.y;
    int tid = threadIdx.x;
    __shared__ float red[8];

    float meanacc[8];
#pragma unroll
    for (int i = 0; i < 8; i++) meanacc[i] = 0.f;

    for (int h = 0; h < NHEAD; h++) {
        float* row = g_P + (((size_t)(b * NHEAD + h)) * SEQ + q) * SEQ;
        float v[8];
        float mx = -3.4e38f;
#pragma unroll
        for (int i = 0; i < 8; i++) {
            v[i] = row[i * 256 + tid];
            mx = fmaxf(mx, v[i]);
        }
#pragma unroll
        for (int o = 16; o > 0; o >>= 1) mx = fmaxf(mx, __shfl_xor_sync(0xFFFFFFFFu, mx, o));
        if ((tid & 31) == 0) red[tid >> 5] = mx;
        __syncthreads();
        float m2 = red[0];
#pragma unroll
        for (int i = 1; i < 8; i++) m2 = fmaxf(m2, red[i]);
        __syncthreads();

        float sum = 0.f;
#pragma unroll
        for (int i = 0; i < 8; i++) {
            v[i] = __expf(v[i] - m2);
            sum += v[i];
        }
#pragma unroll
        for (int o = 16; o > 0; o >>= 1) sum += __shfl_xor_sync(0xFFFFFFFFu, sum, o);
        if ((tid & 31) == 0) red[tid >> 5] = sum;
        __syncthreads();
        float s2 = 0.f;
#pragma unroll
        for (int i = 0; i < 8; i++) s2 += red[i];
        __syncthreads();

        float inv = 1.0f / s2;
#pragma unroll
        for (int i = 0; i < 8; i++) {
            float p = v[i] * inv;
            row[i * 256 + tid] = p;
            meanacc[i] += p;
        }
    }

    float* om = out_mean + ((size_t)(b * SEQ + q)) * SEQ;
    const float invH = 1.0f / NHEAD;
#pragma unroll
    for (int i = 0; i < 8; i++) om[i * 256 + tid] = meanacc[i] * invH;
}

// =====================================================================
// Context: C = P @ V (NN), per (b,h). 128x64 tile, K-tile 16, dbl-buffered.
// grid (1, S/128, B*H), 256 threads, 8x4 micro-tile.
// =====================================================================
__global__ __launch_bounds__(256, 2) void ctx_kernel() {
    __shared__ __align__(16) float As[2][16][132];
    __shared__ __align__(16) float Bs[2][16][68];

    const int bh = blockIdx.z;
    const int b = bh >> 4, h = bh & 15;
    const float* A = g_P + (size_t)bh * SEQ * SEQ;
    const float* V = g_V + (size_t)bh * SEQ * DK;

    const int tid = threadIdx.x;
    const int m0 = blockIdx.y * 128;
    const int ldr = tid >> 1, ldc = (tid & 1) * 8;
    const int bk = tid >> 4, bn4 = (tid & 15) * 4;
    const int tx = tid & 15, ty = tid >> 4;

    const float* Aptr = A + (size_t)(m0 + ldr) * SEQ + ldc;

    {
        float4 a0 = *(const float4*)(Aptr);
        float4 a1 = *(const float4*)(Aptr + 4);
        As[0][ldc+0][ldr]=a0.x; As[0][ldc+1][ldr]=a0.y; As[0][ldc+2][ldr]=a0.z; As[0][ldc+3][ldr]=a0.w;
        As[0][ldc+4][ldr]=a1.x; As[0][ldc+5][ldr]=a1.y; As[0][ldc+6][ldr]=a1.z; As[0][ldc+7][ldr]=a1.w;
        float4 bv = *(const float4*)(V + bk * DK + bn4);
        *(float4*)&Bs[0][bk][bn4] = bv;
    }
    __syncthreads();

    float acc[8][4];
#pragma unroll
    for (int i = 0; i < 8; i++)
#pragma unroll
        for (int j = 0; j < 4; j++) acc[i][j] = 0.f;

    const int ntiles = SEQ >> 4;
    for (int t = 0; t < ntiles; t++) {
        const int cur = t & 1;
        float4 na0, na1, nbv;
        if (t + 1 < ntiles) {
            const float* ap = Aptr + (t + 1) * 16;
            na0 = *(const float4*)(ap);
            na1 = *(const float4*)(ap + 4);
            nbv = *(const float4*)(V + (size_t)((t + 1) * 16 + bk) * DK + bn4);
        }
#pragma unroll
        for (int kk = 0; kk < 16; kk++) {
            float4 av0 = *(const float4*)&As[cur][kk][ty * 4];
            float4 av1 = *(const float4*)&As[cur][kk][64 + ty * 4];
            float4 bv  = *(const float4*)&Bs[cur][kk][tx * 4];
            float am[8] = {av0.x,av0.y,av0.z,av0.w, av1.x,av1.y,av1.z,av1.w};
            float bn[4] = {bv.x, bv.y, bv.z, bv.w};
#pragma unroll
            for (int i = 0; i < 8; i++)
#pragma unroll
                for (int j = 0; j < 4; j++) acc[i][j] += am[i] * bn[j];
        }
        if (t + 1 < ntiles) {
            const int nx = cur ^ 1;
            As[nx][ldc+0][ldr]=na0.x; As[nx][ldc+1][ldr]=na0.y; As[nx][ldc+2][ldr]=na0.z; As[nx][ldc+3][ldr]=na0.w;
            As[nx][ldc+4][ldr]=na1.x; As[nx][ldc+5][ldr]=na1.y; As[nx][ldc+6][ldr]=na1.z; As[nx][ldc+7][ldr]=na1.w;
            *(float4*)&Bs[nx][bk][bn4] = nbv;
        }
        __syncthreads();
    }

#pragma unroll
    for (int gi = 0; gi < 2; gi++)
#pragma unroll
        for (int i = 0; i < 4; i++) {
            int m = m0 + gi * 64 + ty * 4 + i;
            float4 v = make_float4(acc[gi*4+i][0], acc[gi*4+i][1], acc[gi*4+i][2], acc[gi*4+i][3]);
            *(float4*)(g_C + ((size_t)b * SEQ + m) * DMODEL + h * DK + tx * 4) = v;
        }
}

// =====================================================================
extern "C" void kernel_launch(void* const* d_in, const int* in_sizes, int n_in,
                              void* d_out, int out_size) {
    const float* query = (const float*)d_in[0];
    const float* key   = (const float*)d_in[1];
    const float* value = (const float*)d_in[2];
    const int*   mask  = (const int*)d_in[3];
    const float* W_q   = (const float*)d_in[4];
    const float* W_k   = (const float*)d_in[5];
    const float* W_v   = (const float*)d_in[6];
    const float* W_o   = (const float*)d_in[7];
    const float* b_o   = (const float*)d_in[8];

    float* out_main = (float*)d_out;                                    // [B,S,D]
    float* out_mean = out_main + (size_t)BATCH * SEQ * DMODEL;          // [B,S,S]

    dim3 blk(256);
    dim3 gproj(DMODEL / 128, (BATCH * SEQ) / 128, 1);

    gemm128<0><<<gproj, blk>>>(query, W_q, nullptr, nullptr, nullptr, 0);
    gemm128<0><<<gproj, blk>>>(key,   W_k, nullptr, nullptr, nullptr, 1);
    gemm128<0><<<gproj, blk>>>(value, W_v, nullptr, nullptr, nullptr, 2);

    gemm128<1><<<dim3(SEQ / 128, SEQ / 128, BATCH * NHEAD), blk>>>(
        nullptr, nullptr, mask, nullptr, nullptr, 0);

    softmax_mean_kernel<<<dim3(SEQ, BATCH), blk>>>(out_mean);

    ctx_kernel<<<dim3(1, SEQ / 128, BATCH * NHEAD), blk>>>();

    gemm128<2><<<gproj, blk>>>(nullptr, W_o, nullptr, b_o, out_main, 0);
}

// round 3
// speedup vs baseline: 1.4263x; 1.1312x over previous
#include <cuda_runtime.h>
#include <cuda_fp16.h>

#define BATCH 4
#define SEQ   2048
#define DMODEL 1024
#define NHEAD 16
#define DK    64
#define SCALE 0.125f

// ---------------- scratch (device globals; no allocation allowed) ----------------
__device__ float  g_Q[(size_t)BATCH * NHEAD * SEQ * DK];
__device__ float  g_K[(size_t)BATCH * NHEAD * SEQ * DK];
__device__ float  g_V[(size_t)BATCH * NHEAD * SEQ * DK];
__device__ __half g_P[(size_t)BATCH * NHEAD * SEQ * SEQ];   // 512 MB unnormalized probs
__device__ float  g_C[(size_t)BATCH * SEQ * DMODEL];        // context [B,S,D]
__device__ float  g_rowsum[(size_t)BATCH * NHEAD * SEQ];    // exp-score row sums

// =====================================================================
__global__ __launch_bounds__(256) void zero_rowsum() {
    int i = blockIdx.x * 1024 + threadIdx.x * 4;
    *(float4*)(g_rowsum + i) = make_float4(0.f, 0.f, 0.f, 0.f);
}

// =====================================================================
// 128x128x16 double-buffered SGEMM computing C = A @ B^T.
// EPI 0: merged QKV projection (which = blockIdx.z), scatter to [b,h,s,dk].
// EPI 1: scores -> p = exp(mask? s*scale) stored fp16 + rowsum atomics.
// EPI 2: out-proj (+bias -> d_out).
// =====================================================================
template<int EPI>
__global__ __launch_bounds__(256, 2) void gemm128(
    const float* __restrict__ Ap0, const float* __restrict__ Ap1,
    const float* __restrict__ Ap2,
    const float* __restrict__ Bp0, const float* __restrict__ Bp1,
    const float* __restrict__ Bp2,
    const int* __restrict__ mask, const float* __restrict__ bias,
    float* __restrict__ Cp)
{
    __shared__ __align__(16) float As[2][16][132];
    __shared__ __align__(16) float Bs[2][16][132];

    const int z = blockIdx.z;
    const float* A; const float* B; int lda, ldb, kdim;
    if constexpr (EPI == 0) {
        A = (z == 0) ? Ap0 : (z == 1) ? Ap1 : Ap2;
        B = (z == 0) ? Bp0 : (z == 1) ? Bp1 : Bp2;
        lda = DMODEL; ldb = DMODEL; kdim = DMODEL;
    } else if constexpr (EPI == 1) {
        A = g_Q + (size_t)z * SEQ * DK;
        B = g_K + (size_t)z * SEQ * DK;
        lda = DK; ldb = DK; kdim = DK;
    } else {
        A = g_C; B = Bp0; lda = DMODEL; ldb = DMODEL; kdim = DMODEL;
    }

    const int tid = threadIdx.x;
    const int m0 = blockIdx.y * 128, n0 = blockIdx.x * 128;
    const int ldr = tid >> 1;            // 0..127
    const int ldc = (tid & 1) * 8;       // 0 or 8
    const int tx = tid & 15, ty = tid >> 4;

    const float* Aptr = A + (size_t)(m0 + ldr) * lda + ldc;
    const float* Bptr = B + (size_t)(n0 + ldr) * ldb + ldc;

    {
        float4 a0 = *(const float4*)(Aptr);
        float4 a1 = *(const float4*)(Aptr + 4);
        float4 b0 = *(const float4*)(Bptr);
        float4 b1 = *(const float4*)(Bptr + 4);
        As[0][ldc+0][ldr]=a0.x; As[0][ldc+1][ldr]=a0.y; As[0][ldc+2][ldr]=a0.z; As[0][ldc+3][ldr]=a0.w;
        As[0][ldc+4][ldr]=a1.x; As[0][ldc+5][ldr]=a1.y; As[0][ldc+6][ldr]=a1.z; As[0][ldc+7][ldr]=a1.w;
        Bs[0][ldc+0][ldr]=b0.x; Bs[0][ldc+1][ldr]=b0.y; Bs[0][ldc+2][ldr]=b0.z; Bs[0][ldc+3][ldr]=b0.w;
        Bs[0][ldc+4][ldr]=b1.x; Bs[0][ldc+5][ldr]=b1.y; Bs[0][ldc+6][ldr]=b1.z; Bs[0][ldc+7][ldr]=b1.w;
    }
    __syncthreads();

    float acc[8][8];
#pragma unroll
    for (int i = 0; i < 8; i++)
#pragma unroll
        for (int j = 0; j < 8; j++) acc[i][j] = 0.f;

    const int ntiles = kdim >> 4;
    for (int t = 0; t < ntiles; t++) {
        const int cur = t & 1;
        float4 na0, na1, nb0, nb1;
        if (t + 1 < ntiles) {
            const float* ap = Aptr + (t + 1) * 16;
            na0 = *(const float4*)(ap);
            na1 = *(const float4*)(ap + 4);
            const float* bp = Bptr + (t + 1) * 16;
            nb0 = *(const float4*)(bp);
            nb1 = *(const float4*)(bp + 4);
        }
#pragma unroll
        for (int kk = 0; kk < 16; kk++) {
            float4 av0 = *(const float4*)&As[cur][kk][ty * 4];
            float4 av1 = *(const float4*)&As[cur][kk][64 + ty * 4];
            float4 bv0 = *(const float4*)&Bs[cur][kk][tx * 4];
            float4 bv1 = *(const float4*)&Bs[cur][kk][64 + tx * 4];
            float am[8] = {av0.x,av0.y,av0.z,av0.w, av1.x,av1.y,av1.z,av1.w};
            float bn[8] = {bv0.x,bv0.y,bv0.z,bv0.w, bv1.x,bv1.y,bv1.z,bv1.w};
#pragma unroll
            for (int i = 0; i < 8; i++)
#pragma unroll
                for (int j = 0; j < 8; j++) acc[i][j] += am[i] * bn[j];
        }
        if (t + 1 < ntiles) {
            const int nx = cur ^ 1;
            As[nx][ldc+0][ldr]=na0.x; As[nx][ldc+1][ldr]=na0.y; As[nx][ldc+2][ldr]=na0.z; As[nx][ldc+3][ldr]=na0.w;
            As[nx][ldc+4][ldr]=na1.x; As[nx][ldc+5][ldr]=na1.y; As[nx][ldc+6][ldr]=na1.z; As[nx][ldc+7][ldr]=na1.w;
            Bs[nx][ldc+0][ldr]=nb0.x; Bs[nx][ldc+1][ldr]=nb0.y; Bs[nx][ldc+2][ldr]=nb0.z; Bs[nx][ldc+3][ldr]=nb0.w;
            Bs[nx][ldc+4][ldr]=nb1.x; Bs[nx][ldc+5][ldr]=nb1.y; Bs[nx][ldc+6][ldr]=nb1.z; Bs[nx][ldc+7][ldr]=nb1.w;
        }
        __syncthreads();
    }

    if constexpr (EPI == 0) {
        float* Out = (z == 0) ? g_Q : (z == 1) ? g_K : g_V;
#pragma unroll
        for (int gi = 0; gi < 2; gi++)
#pragma unroll
            for (int i = 0; i < 4; i++) {
                int m = m0 + gi * 64 + ty * 4 + i;
                int b = m >> 11, s = m & (SEQ - 1);
#pragma unroll
                for (int gj = 0; gj < 2; gj++) {
                    int n = n0 + gj * 64 + tx * 4;
                    int h = n >> 6, dk = n & 63;
                    float4 v = make_float4(acc[gi*4+i][gj*4+0], acc[gi*4+i][gj*4+1],
                                           acc[gi*4+i][gj*4+2], acc[gi*4+i][gj*4+3]);
                    *(float4*)(Out + (((size_t)b * NHEAD + h) * SEQ + s) * DK + dk) = v;
                }
            }
    } else if constexpr (EPI == 1) {
        const int b = z >> 4;
        __half* C = g_P + (size_t)z * SEQ * SEQ;
        int mk[2][4];
#pragma unroll
        for (int gj = 0; gj < 2; gj++)
#pragma unroll
            for (int j = 0; j < 4; j++)
                mk[gj][j] = mask[b * SEQ + n0 + gj * 64 + tx * 4 + j];

        float rsum[8];
#pragma unroll
        for (int i = 0; i < 8; i++) rsum[i] = 0.f;

#pragma unroll
        for (int gi = 0; gi < 2; gi++)
#pragma unroll
            for (int i = 0; i < 4; i++) {
                int m = m0 + gi * 64 + ty * 4 + i;
#pragma unroll
                for (int gj = 0; gj < 2; gj++) {
                    int n = n0 + gj * 64 + tx * 4;
                    float p0 = mk[gj][0] ? __expf(acc[gi*4+i][gj*4+0] * SCALE) : 0.f;
                    float p1 = mk[gj][1] ? __expf(acc[gi*4+i][gj*4+1] * SCALE) : 0.f;
                    float p2 = mk[gj][2] ? __expf(acc[gi*4+i][gj*4+2] * SCALE) : 0.f;
                    float p3 = mk[gj][3] ? __expf(acc[gi*4+i][gj*4+3] * SCALE) : 0.f;
                    rsum[gi*4+i] += (p0 + p1) + (p2 + p3);
                    __half2 h0 = __floats2half2_rn(p0, p1);
                    __half2 h1 = __floats2half2_rn(p2, p3);
                    uint2 pk;
                    pk.x = *(unsigned int*)&h0;
                    pk.y = *(unsigned int*)&h1;
                    *(uint2*)(C + (size_t)m * SEQ + n) = pk;
                }
            }
        // reduce rsum over the 16 tx lanes (same ty -> contiguous 16 lanes in warp)
#pragma unroll
        for (int i = 0; i < 8; i++) {
#pragma unroll
            for (int o = 8; o > 0; o >>= 1)
                rsum[i] += __shfl_xor_sync(0xFFFFFFFFu, rsum[i], o);
        }
        if (tx == 0) {
#pragma unroll
            for (int gi = 0; gi < 2; gi++)
#pragma unroll
                for (int i = 0; i < 4; i++) {
                    int m = m0 + gi * 64 + ty * 4 + i;
                    atomicAdd(&g_rowsum[(size_t)z * SEQ + m], rsum[gi*4+i]);
                }
        }
    } else {
#pragma unroll
        for (int gi = 0; gi < 2; gi++)
#pragma unroll
            for (int i = 0; i < 4; i++) {
                int m = m0 + gi * 64 + ty * 4 + i;
#pragma unroll
                for (int gj = 0; gj < 2; gj++) {
                    int n = n0 + gj * 64 + tx * 4;
                    float4 bb = *(const float4*)(bias + n);
                    float4 v = make_float4(acc[gi*4+i][gj*4+0] + bb.x, acc[gi*4+i][gj*4+1] + bb.y,
                                           acc[gi*4+i][gj*4+2] + bb.z, acc[gi*4+i][gj*4+3] + bb.w);
                    *(float4*)(Cp + (size_t)m * DMODEL + n) = v;
                }
            }
    }
}

// =====================================================================
// Head-mean of normalized probs: out_mean[b,q,:] = (1/H) sum_h p_h * inv_h.
// grid (SEQ, BATCH), 256 threads; half2 loads.
// =====================================================================
__global__ __launch_bounds__(256) void mean_kernel(float* __restrict__ out_mean) {
    int q = blockIdx.x;
    int b = blockIdx.y;
    int tid = threadIdx.x;

    float2 macc[4];
#pragma unroll
    for (int j = 0; j < 4; j++) macc[j] = make_float2(0.f, 0.f);

#pragma unroll 1
    for (int h = 0; h < NHEAD; h++) {
        const __half2* row = (const __half2*)(g_P + (((size_t)(b * NHEAD + h)) * SEQ + q) * SEQ);
        float inv = 1.0f / g_rowsum[(size_t)(b * NHEAD + h) * SEQ + q];
#pragma unroll
        for (int j = 0; j < 4; j++) {
            float2 f = __half22float2(row[j * 256 + tid]);
            macc[j].x += f.x * inv;
            macc[j].y += f.y * inv;
        }
    }

    float* om = out_mean + ((size_t)(b * SEQ + q)) * SEQ;
    const float invH = 1.0f / NHEAD;
#pragma unroll
    for (int j = 0; j < 4; j++) {
        float2 v = make_float2(macc[j].x * invH, macc[j].y * invH);
        *(float2*)(om + (j * 256 + tid) * 2) = v;
    }
}

// =====================================================================
// Context: C = (P @ V) * invsum, per (b,h). 128x64 tile, fp16 A operand.
// grid (1, S/128, B*H), 256 threads, 8x4 micro-tile.
// =====================================================================
__global__ __launch_bounds__(256, 2) void ctx_kernel() {
    __shared__ __align__(16) float As[2][16][132];
    __shared__ __align__(16) float Bs[2][16][68];

    const int bh = blockIdx.z;
    const int b = bh >> 4, h = bh & 15;
    const __half* A = g_P + (size_t)bh * SEQ * SEQ;
    const float* V = g_V + (size_t)bh * SEQ * DK;

    const int tid = threadIdx.x;
    const int m0 = blockIdx.y * 128;
    const int ldr = tid >> 1, ldc = (tid & 1) * 8;
    const int bk = tid >> 4, bn4 = (tid & 15) * 4;
    const int tx = tid & 15, ty = tid >> 4;

    const __half* Aptr = A + (size_t)(m0 + ldr) * SEQ + ldc;

    {
        uint4 raw = *(const uint4*)(Aptr);
        const __half2* hh = (const __half2*)&raw;
#pragma unroll
        for (int t2 = 0; t2 < 4; t2++) {
            float2 f = __half22float2(hh[t2]);
            As[0][ldc + t2*2 + 0][ldr] = f.x;
            As[0][ldc + t2*2 + 1][ldr] = f.y;
        }
        float4 bv = *(const float4*)(V + bk * DK + bn4);
        *(float4*)&Bs[0][bk][bn4] = bv;
    }
    __syncthreads();

    float acc[8][4];
#pragma unroll
    for (int i = 0; i < 8; i++)
#pragma unroll
        for (int j = 0; j < 4; j++) acc[i][j] = 0.f;

    const int ntiles = SEQ >> 4;
    for (int t = 0; t < ntiles; t++) {
        const int cur = t & 1;
        uint4 nraw; float4 nbv;
        if (t + 1 < ntiles) {
            nraw = *(const uint4*)(Aptr + (t + 1) * 16);
            nbv = *(const float4*)(V + (size_t)((t + 1) * 16 + bk) * DK + bn4);
        }
#pragma unroll
        for (int kk = 0; kk < 16; kk++) {
            float4 av0 = *(const float4*)&As[cur][kk][ty * 4];
            float4 av1 = *(const float4*)&As[cur][kk][64 + ty * 4];
            float4 bv  = *(const float4*)&Bs[cur][kk][tx * 4];
            float am[8] = {av0.x,av0.y,av0.z,av0.w, av1.x,av1.y,av1.z,av1.w};
            float bn[4] = {bv.x, bv.y, bv.z, bv.w};
#pragma unroll
            for (int i = 0; i < 8; i++)
#pragma unroll
                for (int j = 0; j < 4; j++) acc[i][j] += am[i] * bn[j];
        }
        if (t + 1 < ntiles) {
            const int nx = cur ^ 1;
            const __half2* hh = (const __half2*)&nraw;
#pragma unroll
            for (int t2 = 0; t2 < 4; t2++) {
                float2 f = __half22float2(hh[t2]);
                As[nx][ldc + t2*2 + 0][ldr] = f.x;
                As[nx][ldc + t2*2 + 1][ldr] = f.y;
            }
            *(float4*)&Bs[nx][bk][bn4] = nbv;
        }
        __syncthreads();
    }

#pragma unroll
    for (int gi = 0; gi < 2; gi++)
#pragma unroll
        for (int i = 0; i < 4; i++) {
            int m = m0 + gi * 64 + ty * 4 + i;
            float inv = 1.0f / g_rowsum[(size_t)bh * SEQ + m];
            float4 v = make_float4(acc[gi*4+i][0] * inv, acc[gi*4+i][1] * inv,
                                   acc[gi*4+i][2] * inv, acc[gi*4+i][3] * inv);
            *(float4*)(g_C + ((size_t)b * SEQ + m) * DMODEL + h * DK + tx * 4) = v;
        }
}

// =====================================================================
extern "C" void kernel_launch(void* const* d_in, const int* in_sizes, int n_in,
                              void* d_out, int out_size) {
    const float* query = (const float*)d_in[0];
    const float* key   = (const float*)d_in[1];
    const float* value = (const float*)d_in[2];
    const int*   mask  = (const int*)d_in[3];
    const float* W_q   = (const float*)d_in[4];
    const float* W_k   = (const float*)d_in[5];
    const float* W_v   = (const float*)d_in[6];
    const float* W_o   = (const float*)d_in[7];
    const float* b_o   = (const float*)d_in[8];

    float* out_main = (float*)d_out;                                    // [B,S,D]
    float* out_mean = out_main + (size_t)BATCH * SEQ * DMODEL;          // [B,S,S]

    dim3 blk(256);

    zero_rowsum<<<BATCH * NHEAD * SEQ / 1024, blk>>>();

    // merged QKV projections
    gemm128<0><<<dim3(DMODEL / 128, (BATCH * SEQ) / 128, 3), blk>>>(
        query, key, value, W_q, W_k, W_v, nullptr, nullptr, nullptr);

    // scores + exp + fp16 store + rowsum
    gemm128<1><<<dim3(SEQ / 128, SEQ / 128, BATCH * NHEAD), blk>>>(
        nullptr, nullptr, nullptr, nullptr, nullptr, nullptr, mask, nullptr, nullptr);

    mean_kernel<<<dim3(SEQ, BATCH), blk>>>(out_mean);

    ctx_kernel<<<dim3(1, SEQ / 128, BATCH * NHEAD), blk>>>();

    // output projection
    gemm128<2><<<dim3(DMODEL / 128, (BATCH * SEQ) / 128, 1), blk>>>(
        nullptr, nullptr, nullptr, W_o, nullptr, nullptr, nullptr, b_o, out_main);
}

// round 7
// speedup vs baseline: 4.4750x; 3.1374x over previous
#include <cuda_runtime.h>
#include <cuda_fp16.h>
#include <cstdint>

#define BATCH 4
#define SEQ   2048
#define DMODEL 1024
#define NHEAD 16
#define DK    64
#define SCALE 0.125f

// ---------------- scratch (device globals; no allocation allowed) ----------------
__device__ __half g_Xh[3][(size_t)BATCH * SEQ * DMODEL];     // fp16 inputs
__device__ __half g_Wh[4][(size_t)DMODEL * DMODEL];          // fp16 weights (q,k,v,o)
__device__ __half g_Qh[(size_t)BATCH * NHEAD * SEQ * DK];    // [b,h,s,dk]
__device__ __half g_Kh[(size_t)BATCH * NHEAD * SEQ * DK];    // [b,h,s,dk]
__device__ __half g_Vt[(size_t)BATCH * NHEAD * DK * SEQ];    // [b,h,dk,s]  (transposed!)
__device__ __half g_P [(size_t)BATCH * NHEAD * SEQ * SEQ];   // 512 MB unnormalized probs
__device__ __half g_Ch[(size_t)BATCH * SEQ * DMODEL];        // context fp16 [B,S,D]
__device__ float  g_rowsum[(size_t)BATCH * NHEAD * SEQ];

// =====================================================================
__global__ __launch_bounds__(256) void zero_rowsum() {
    int i = blockIdx.x * 1024 + threadIdx.x * 4;
    *(float4*)(g_rowsum + i) = make_float4(0.f, 0.f, 0.f, 0.f);
}

// dst selected inside the kernel: which 0..2 -> g_Xh[which], 3..6 -> g_Wh[which-3]
__global__ __launch_bounds__(256) void cvt_kernel(const float* __restrict__ s,
                                                  int which, int n4) {
    int i = blockIdx.x * 256 + threadIdx.x;
    if (i < n4) {
        __half* d = (which < 3) ? g_Xh[which] : g_Wh[which - 3];
        float4 v = ((const float4*)s)[i];
        __half2* dp = (__half2*)d + i * 2;
        dp[0] = __floats2half2_rn(v.x, v.y);
        dp[1] = __floats2half2_rn(v.z, v.w);
    }
}

// ---------------- mma helpers ----------------
__device__ __forceinline__ uint32_t smaddr(const void* p) {
    return (uint32_t)__cvta_generic_to_shared(p);
}
__device__ __forceinline__ void ldsm4(uint32_t& a0, uint32_t& a1, uint32_t& a2, uint32_t& a3,
                                      uint32_t addr) {
    asm volatile("ldmatrix.sync.aligned.m8n8.x4.shared.b16 {%0,%1,%2,%3}, [%4];\n"
                 : "=r"(a0), "=r"(a1), "=r"(a2), "=r"(a3) : "r"(addr));
}
__device__ __forceinline__ void ldsm2(uint32_t& b0, uint32_t& b1, uint32_t addr) {
    asm volatile("ldmatrix.sync.aligned.m8n8.x2.shared.b16 {%0,%1}, [%2];\n"
                 : "=r"(b0), "=r"(b1) : "r"(addr));
}
__device__ __forceinline__ void mma16816(float* c, uint32_t a0, uint32_t a1, uint32_t a2,
                                         uint32_t a3, uint32_t b0, uint32_t b1) {
    asm volatile("mma.sync.aligned.m16n8k16.row.col.f32.f16.f16.f32 "
                 "{%0,%1,%2,%3}, {%4,%5,%6,%7}, {%8,%9}, {%0,%1,%2,%3};\n"
                 : "+f"(c[0]), "+f"(c[1]), "+f"(c[2]), "+f"(c[3])
                 : "r"(a0), "r"(a1), "r"(a2), "r"(a3), "r"(b0), "r"(b1));
}

#define LDS 40   // padded leading dim (halfs): conflict-free ldmatrix

// =====================================================================
// 128x128 HMMA GEMM: C = A @ B^T, A [M,kd] row fp16, B [N,kd] row fp16.
// 8 warps: wy = wid>>2 (m 64), wx = wid&3 (n 32). mma tiles 4x4 per warp.
// EPI 0: QKV proj (z=which; V written transposed).
// EPI 1: scores -> exp -> fp16 P + rowsum.  EPI 2: out-proj fp32 + bias.
// =====================================================================
template<int EPI>
__global__ __launch_bounds__(256) void mgemm(const int* __restrict__ mask,
                                             const float* __restrict__ bias,
                                             float* __restrict__ Cp) {
    __shared__ __align__(16) __half As[2][128 * LDS];
    __shared__ __align__(16) __half Bs[2][128 * LDS];

    const int z = blockIdx.z;
    const __half* A; const __half* B; int lda, ktiles;
    if constexpr (EPI == 0) { A = g_Xh[z]; B = g_Wh[z]; lda = DMODEL; ktiles = DMODEL / 32; }
    else if constexpr (EPI == 1) {
        A = g_Qh + (size_t)z * SEQ * DK;
        B = g_Kh + (size_t)z * SEQ * DK;
        lda = DK; ktiles = 2;
    } else { A = g_Ch; B = g_Wh[3]; lda = DMODEL; ktiles = DMODEL / 32; }

    const int tid = threadIdx.x;
    const int m0 = blockIdx.y * 128, n0 = blockIdx.x * 128;
    const int wid = tid >> 5, lane = tid & 31;
    const int wy = wid >> 2, wx = wid & 3;

    // loader: ids tid and tid+256; row = id>>2, chunk = id&3 (8 halfs)
    const int r0 = tid >> 2, c0 = (tid & 3) * 8;
    const int r1 = (tid + 256) >> 2, c1 = c0;

    const __half* Ag0 = A + (size_t)(m0 + r0) * lda + c0;
    const __half* Ag1 = A + (size_t)(m0 + r1) * lda + c1;
    const __half* Bg0 = B + (size_t)(n0 + r0) * lda + c0;
    const __half* Bg1 = B + (size_t)(n0 + r1) * lda + c1;

    // preload tile 0
    {
        uint4 a0 = *(const uint4*)Ag0, a1 = *(const uint4*)Ag1;
        uint4 b0 = *(const uint4*)Bg0, b1 = *(const uint4*)Bg1;
        *(uint4*)&As[0][r0 * LDS + c0] = a0; *(uint4*)&As[0][r1 * LDS + c1] = a1;
        *(uint4*)&Bs[0][r0 * LDS + c0] = b0; *(uint4*)&Bs[0][r1 * LDS + c1] = b1;
    }
    __syncthreads();

    // ldmatrix element offsets (per k-step add ks*16)
    int aoff[4], boff[4];
#pragma unroll
    for (int mt = 0; mt < 4; mt++)
        aoff[mt] = (wy * 64 + mt * 16 + (lane & 15)) * LDS + (lane >> 4) * 8;
#pragma unroll
    for (int nt = 0; nt < 4; nt++)
        boff[nt] = (wx * 32 + nt * 8 + (lane & 7)) * LDS + ((lane >> 3) & 1) * 8;

    float acc[4][4][4];
#pragma unroll
    for (int i = 0; i < 4; i++)
#pragma unroll
        for (int j = 0; j < 4; j++)
#pragma unroll
            for (int k = 0; k < 4; k++) acc[i][j][k] = 0.f;

    for (int t = 0; t < ktiles; t++) {
        const int cur = t & 1;
        uint4 pa0, pa1, pb0, pb1;
        if (t + 1 < ktiles) {
            int ko = (t + 1) * 32;
            pa0 = *(const uint4*)(Ag0 + ko); pa1 = *(const uint4*)(Ag1 + ko);
            pb0 = *(const uint4*)(Bg0 + ko); pb1 = *(const uint4*)(Bg1 + ko);
        }
#pragma unroll
        for (int ks = 0; ks < 2; ks++) {
            uint32_t af[4][4], bf[4][2];
#pragma unroll
            for (int mt = 0; mt < 4; mt++)
                ldsm4(af[mt][0], af[mt][1], af[mt][2], af[mt][3],
                      smaddr(&As[cur][aoff[mt] + ks * 16]));
#pragma unroll
            for (int nt = 0; nt < 4; nt++)
                ldsm2(bf[nt][0], bf[nt][1], smaddr(&Bs[cur][boff[nt] + ks * 16]));
#pragma unroll
            for (int mt = 0; mt < 4; mt++)
#pragma unroll
                for (int nt = 0; nt < 4; nt++)
                    mma16816(acc[mt][nt], af[mt][0], af[mt][1], af[mt][2], af[mt][3],
                             bf[nt][0], bf[nt][1]);
        }
        if (t + 1 < ktiles) {
            const int nx = cur ^ 1;
            *(uint4*)&As[nx][r0 * LDS + c0] = pa0; *(uint4*)&As[nx][r1 * LDS + c1] = pa1;
            *(uint4*)&Bs[nx][r0 * LDS + c0] = pb0; *(uint4*)&Bs[nx][r1 * LDS + c1] = pb1;
        }
        __syncthreads();
    }

    // ---------------- epilogues ----------------
    if constexpr (EPI == 0) {
#pragma unroll
        for (int mt = 0; mt < 4; mt++) {
            int rA = m0 + wy * 64 + mt * 16 + (lane >> 2);
#pragma unroll
            for (int half_ = 0; half_ < 2; half_++) {
                int r = rA + half_ * 8;
                int b = r >> 11, s = r & (SEQ - 1);
#pragma unroll
                for (int nt = 0; nt < 4; nt++) {
                    int c = n0 + wx * 32 + nt * 8 + (lane & 3) * 2;
                    int h = c >> 6, dk = c & 63;
                    float v0 = acc[mt][nt][half_ * 2 + 0];
                    float v1 = acc[mt][nt][half_ * 2 + 1];
                    if (z == 2) {
                        size_t base = ((size_t)(b * NHEAD + h) * DK + dk) * SEQ + s;
                        g_Vt[base] = __float2half_rn(v0);
                        g_Vt[base + SEQ] = __float2half_rn(v1);
                    } else {
                        __half* Out = (z == 0) ? g_Qh : g_Kh;
                        *(__half2*)(Out + ((size_t)(b * NHEAD + h) * SEQ + s) * DK + dk) =
                            __floats2half2_rn(v0, v1);
                    }
                }
            }
        }
    } else if constexpr (EPI == 1) {
        const int b = z >> 4;
        __half* P = g_P + (size_t)z * SEQ * SEQ;
#pragma unroll
        for (int mt = 0; mt < 4; mt++) {
            int rA = m0 + wy * 64 + mt * 16 + (lane >> 2);
            float rs[2] = {0.f, 0.f};
#pragma unroll
            for (int nt = 0; nt < 4; nt++) {
                int c = n0 + wx * 32 + nt * 8 + (lane & 3) * 2;
                int mk0 = mask[b * SEQ + c], mk1 = mask[b * SEQ + c + 1];
#pragma unroll
                for (int half_ = 0; half_ < 2; half_++) {
                    int r = rA + half_ * 8;
                    float p0 = mk0 ? __expf(acc[mt][nt][half_ * 2 + 0] * SCALE) : 0.f;
                    float p1 = mk1 ? __expf(acc[mt][nt][half_ * 2 + 1] * SCALE) : 0.f;
                    rs[half_] += p0 + p1;
                    *(__half2*)(P + (size_t)r * SEQ + c) = __floats2half2_rn(p0, p1);
                }
            }
            rs[0] += __shfl_xor_sync(0xFFFFFFFFu, rs[0], 1);
            rs[0] += __shfl_xor_sync(0xFFFFFFFFu, rs[0], 2);
            rs[1] += __shfl_xor_sync(0xFFFFFFFFu, rs[1], 1);
            rs[1] += __shfl_xor_sync(0xFFFFFFFFu, rs[1], 2);
            if ((lane & 3) == 0) {
                atomicAdd(&g_rowsum[(size_t)z * SEQ + rA], rs[0]);
                atomicAdd(&g_rowsum[(size_t)z * SEQ + rA + 8], rs[1]);
            }
        }
    } else {
#pragma unroll
        for (int mt = 0; mt < 4; mt++) {
            int rA = m0 + wy * 64 + mt * 16 + (lane >> 2);
#pragma unroll
            for (int half_ = 0; half_ < 2; half_++) {
                int r = rA + half_ * 8;
#pragma unroll
                for (int nt = 0; nt < 4; nt++) {
                    int c = n0 + wx * 32 + nt * 8 + (lane & 3) * 2;
                    float2 bb = *(const float2*)(bias + c);
                    float2 v = make_float2(acc[mt][nt][half_ * 2 + 0] + bb.x,
                                           acc[mt][nt][half_ * 2 + 1] + bb.y);
                    *(float2*)(Cp + (size_t)r * DMODEL + c) = v;
                }
            }
        }
    }
}

// =====================================================================
// Context via HMMA: C = (P @ V) * invsum. A = P [S,S] fp16, B = Vt [64,S] fp16.
// CTA 128(m) x 64(n), 8 warps: wy=wid>>1 (m 32), wx=wid&1 (n 32). tiles 2x4.
// =====================================================================
__global__ __launch_bounds__(256) void ctx_mma() {
    __shared__ __align__(16) __half As[2][128 * LDS];
    __shared__ __align__(16) __half Bs[2][64 * LDS];

    const int bh = blockIdx.z;
    const int b = bh >> 4, h = bh & 15;
    const __half* A = g_P + (size_t)bh * SEQ * SEQ;
    const __half* Bt = g_Vt + (size_t)bh * DK * SEQ;

    const int tid = threadIdx.x;
    const int m0 = blockIdx.y * 128;
    const int wid = tid >> 5, lane = tid & 31;
    const int wy = wid >> 1, wx = wid & 1;

    const int r0 = tid >> 2, c0 = (tid & 3) * 8;       // A rows 0..63
    const int r1 = (tid + 256) >> 2;                   // A rows 64..127
    const int rB = tid >> 2;                           // B rows 0..63

    const __half* Ag0 = A + (size_t)(m0 + r0) * SEQ + c0;
    const __half* Ag1 = A + (size_t)(m0 + r1) * SEQ + c0;
    const __half* Bg0 = Bt + (size_t)rB * SEQ + c0;

    {
        uint4 a0 = *(const uint4*)Ag0, a1 = *(const uint4*)Ag1;
        uint4 b0 = *(const uint4*)Bg0;
        *(uint4*)&As[0][r0 * LDS + c0] = a0;
        *(uint4*)&As[0][r1 * LDS + c0] = a1;
        *(uint4*)&Bs[0][r0 * LDS + c0] = b0;
    }
    __syncthreads();

    int aoff[2], boff[4];
#pragma unroll
    for (int mt = 0; mt < 2; mt++)
        aoff[mt] = (wy * 32 + mt * 16 + (lane & 15)) * LDS + (lane >> 4) * 8;
#pragma unroll
    for (int nt = 0; nt < 4; nt++)
        boff[nt] = (wx * 32 + nt * 8 + (lane & 7)) * LDS + ((lane >> 3) & 1) * 8;

    float acc[2][4][4];
#pragma unroll
    for (int i = 0; i < 2; i++)
#pragma unroll
        for (int j = 0; j < 4; j++)
#pragma unroll
            for (int k = 0; k < 4; k++) acc[i][j][k] = 0.f;

    const int ktiles = SEQ / 32;
    for (int t = 0; t < ktiles; t++) {
        const int cur = t & 1;
        uint4 pa0, pa1, pb0;
        if (t + 1 < ktiles) {
            int ko = (t + 1) * 32;
            pa0 = *(const uint4*)(Ag0 + ko);
            pa1 = *(const uint4*)(Ag1 + ko);
            pb0 = *(const uint4*)(Bg0 + ko);
        }
#pragma unroll
        for (int ks = 0; ks < 2; ks++) {
            uint32_t af[2][4], bf[4][2];
#pragma unroll
            for (int mt = 0; mt < 2; mt++)
                ldsm4(af[mt][0], af[mt][1], af[mt][2], af[mt][3],
                      smaddr(&As[cur][aoff[mt] + ks * 16]));
#pragma unroll
            for (int nt = 0; nt < 4; nt++)
                ldsm2(bf[nt][0], bf[nt][1], smaddr(&Bs[cur][boff[nt] + ks * 16]));
#pragma unroll
            for (int mt = 0; mt < 2; mt++)
#pragma unroll
                for (int nt = 0; nt < 4; nt++)
                    mma16816(acc[mt][nt], af[mt][0], af[mt][1], af[mt][2], af[mt][3],
                             bf[nt][0], bf[nt][1]);
        }
        if (t + 1 < ktiles) {
            const int nx = cur ^ 1;
            *(uint4*)&As[nx][r0 * LDS + c0] = pa0;
            *(uint4*)&As[nx][r1 * LDS + c0] = pa1;
            *(uint4*)&Bs[nx][r0 * LDS + c0] = pb0;
        }
        __syncthreads();
    }

#pragma unroll
    for (int mt = 0; mt < 2; mt++) {
        int rA = m0 + wy * 32 + mt * 16 + (lane >> 2);
#pragma unroll
        for (int half_ = 0; half_ < 2; half_++) {
            int r = rA + half_ * 8;
            float inv = 1.0f / g_rowsum[(size_t)bh * SEQ + r];
#pragma unroll
            for (int nt = 0; nt < 4; nt++) {
                int c = wx * 32 + nt * 8 + (lane & 3) * 2;
                *(__half2*)(g_Ch + ((size_t)(b * SEQ + r)) * DMODEL + h * DK + c) =
                    __floats2half2_rn(acc[mt][nt][half_ * 2 + 0] * inv,
                                      acc[mt][nt][half_ * 2 + 1] * inv);
            }
        }
    }
}

// =====================================================================
// Head-mean of normalized probs (memory-bound).
// =====================================================================
__global__ __launch_bounds__(256) void mean_kernel(float* __restrict__ out_mean) {
    int q = blockIdx.x;
    int b = blockIdx.y;
    int tid = threadIdx.x;

    float2 macc[4];
#pragma unroll
    for (int j = 0; j < 4; j++) macc[j] = make_float2(0.f, 0.f);

#pragma unroll 1
    for (int h = 0; h < NHEAD; h++) {
        const __half2* row = (const __half2*)(g_P + (((size_t)(b * NHEAD + h)) * SEQ + q) * SEQ);
        float inv = 1.0f / g_rowsum[(size_t)(b * NHEAD + h) * SEQ + q];
#pragma unroll
        for (int j = 0; j < 4; j++) {
            float2 f = __half22float2(row[j * 256 + tid]);
            macc[j].x += f.x * inv;
            macc[j].y += f.y * inv;
        }
    }

    float* om = out_mean + ((size_t)(b * SEQ + q)) * SEQ;
    const float invH = 1.0f / NHEAD;
#pragma unroll
    for (int j = 0; j < 4; j++) {
        float2 v = make_float2(macc[j].x * invH, macc[j].y * invH);
        *(float2*)(om + (j * 256 + tid) * 2) = v;
    }
}

// =====================================================================
extern "C" void kernel_launch(void* const* d_in, const int* in_sizes, int n_in,
                              void* d_out, int out_size) {
    const float* query = (const float*)d_in[0];
    const float* key   = (const float*)d_in[1];
    const float* value = (const float*)d_in[2];
    const int*   mask  = (const int*)d_in[3];
    const float* W_q   = (const float*)d_in[4];
    const float* W_k   = (const float*)d_in[5];
    const float* W_v   = (const float*)d_in[6];
    const float* W_o   = (const float*)d_in[7];
    const float* b_o   = (const float*)d_in[8];

    float* out_main = (float*)d_out;                                    // [B,S,D]
    float* out_mean = out_main + (size_t)BATCH * SEQ * DMODEL;          // [B,S,S]

    dim3 blk(256);

    zero_rowsum<<<BATCH * NHEAD * SEQ / 1024, blk>>>();

    // fp16 conversions (dst resolved inside kernel; no host symbol queries)
    const int nX4 = BATCH * SEQ * DMODEL / 4;     // 2M
    const int nW4 = DMODEL * DMODEL / 4;          // 256K
    cvt_kernel<<<(nX4 + 255) / 256, blk>>>(query, 0, nX4);
    cvt_kernel<<<(nX4 + 255) / 256, blk>>>(key,   1, nX4);
    cvt_kernel<<<(nX4 + 255) / 256, blk>>>(value, 2, nX4);
    cvt_kernel<<<(nW4 + 255) / 256, blk>>>(W_q, 3, nW4);
    cvt_kernel<<<(nW4 + 255) / 256, blk>>>(W_k, 4, nW4);
    cvt_kernel<<<(nW4 + 255) / 256, blk>>>(W_v, 5, nW4);
    cvt_kernel<<<(nW4 + 255) / 256, blk>>>(W_o, 6, nW4);

    // QKV projections (z = which)
    mgemm<0><<<dim3(DMODEL / 128, (BATCH * SEQ) / 128, 3), blk>>>(nullptr, nullptr, nullptr);

    // scores + exp + fp16 P + rowsum
    mgemm<1><<<dim3(SEQ / 128, SEQ / 128, BATCH * NHEAD), blk>>>(mask, nullptr, nullptr);

    mean_kernel<<<dim3(SEQ, BATCH), blk>>>(out_mean);

    ctx_mma<<<dim3(1, SEQ / 128, BATCH * NHEAD), blk>>>();

    // output projection
    mgemm<2><<<dim3(DMODEL / 128, (BATCH * SEQ) / 128, 1), blk>>>(nullptr, b_o, out_main);
}